// round 2
// baseline (speedup 1.0000x reference)
#include <cuda_runtime.h>
#include <cstdint>

#define LOG2E     1.4426950408889634f
#define TWO_LOG2E 2.8853900817779268f
#define GRU_CTAS  128

// ---------------- scratch (device globals: no allocation allowed) ----------
__device__ float    g_gi[2400 * 768];   // pre-GRU input gates  [t*8+n][768]
__device__ float    g_u2[1280 * 256];   // 2*log2e * (memory @ U^T)  [n*160+x][256]
__device__ float    g_w2[2400 * 256];   // 2*log2e * (outputs @ W^T) [n*300+t][256]
__device__ float    g_hb[2 * 8 * 256];  // ping-pong hidden state
__device__ unsigned g_bar[304];         // per-step grid barrier counters

// ---------------- fast math ------------------------------------------------
__device__ __forceinline__ float ex2f_(float x) {
    float y; asm("ex2.approx.f32 %0, %1;" : "=f"(y) : "f"(x)); return y;
}
__device__ __forceinline__ float rcpf_(float x) {
    float y; asm("rcp.approx.f32 %0, %1;" : "=f"(y) : "f"(x)); return y;
}
__device__ __forceinline__ float sigmoidf_(float x) {
    return rcpf_(1.f + ex2f_(-x * LOG2E));
}
__device__ __forceinline__ float tanhf_(float x) {
    // tanh(x) = 1 - 2/(exp(2x)+1); exact at +-inf, ~1e-6 error
    return fmaf(-2.f, rcpf_(1.f + ex2f_(x * TWO_LOG2E)), 1.f);
}

// ---------------- kernel A: gi = inputs @ Wih^T + bih (+bhh for r,z) -------
// out rows indexed i = t*8 + n ; grid (150, 3), block 256
// NOTE: bhh is folded ONLY for gates r,z (jb<2). The n-gate's recurrent bias
// must stay inside the reset-gate product: n = tanh(i_n + r*(hdot + bhh_n)).
__global__ void gi_kernel(const float* __restrict__ inp,
                          const float* __restrict__ Wih,
                          const float* __restrict__ bih,
                          const float* __restrict__ bhh) {
    __shared__ float xs[16][128];
    int tid = threadIdx.x;
    int ib = blockIdx.x, jb = blockIdx.y;
    int j = jb * 256 + tid;

    for (int q = 0; q < 2; q++) {
        int f4 = tid + 256 * q;          // 0..511 float4 slots (16 rows * 32)
        int ii = f4 >> 5, pos = f4 & 31;
        int i = ib * 16 + ii;
        int t = i >> 3, n = i & 7;
        ((float4*)xs[ii])[pos] = ((const float4*)(inp + (n * 300 + t) * 128))[pos];
    }
    __syncthreads();

    float acc[16];
#pragma unroll
    for (int ii = 0; ii < 16; ii++) acc[ii] = 0.f;

    const float4* wr = (const float4*)(Wih + (size_t)j * 128);
    for (int k4 = 0; k4 < 32; k4++) {
        float4 w4 = __ldg(wr + k4);
#pragma unroll
        for (int ii = 0; ii < 16; ii++) {
            float4 xv = ((const float4*)xs[ii])[k4];
            acc[ii] = fmaf(w4.x, xv.x, acc[ii]);
            acc[ii] = fmaf(w4.y, xv.y, acc[ii]);
            acc[ii] = fmaf(w4.z, xv.z, acc[ii]);
            acc[ii] = fmaf(w4.w, xv.w, acc[ii]);
        }
    }
    float b = bih[j] + (jb < 2 ? bhh[j] : 0.f);
#pragma unroll
    for (int ii = 0; ii < 16; ii++)
        g_gi[(size_t)(ib * 16 + ii) * 768 + j] = acc[ii] + b;
}

// ---------------- shared 256-K GEMM body: out[i][j] = scale * A_i . B_j ----
__device__ __forceinline__ void gemm256_body(const float* __restrict__ A,
                                             const float* __restrict__ B,
                                             float* __restrict__ out,
                                             float scale) {
    __shared__ float xs[16][256];
    int tid = threadIdx.x, ib = blockIdx.x;
    for (int q = 0; q < 4; q++) {
        int f4 = tid + 256 * q;          // 0..1023 (16 rows * 64)
        int ii = f4 >> 6, pos = f4 & 63;
        ((float4*)xs[ii])[pos] = ((const float4*)(A + (size_t)(ib * 16 + ii) * 256))[pos];
    }
    __syncthreads();

    float acc[16];
#pragma unroll
    for (int ii = 0; ii < 16; ii++) acc[ii] = 0.f;

    const float4* br = (const float4*)(B + (size_t)tid * 256);
    for (int k4 = 0; k4 < 64; k4++) {
        float4 b4 = __ldg(br + k4);
#pragma unroll
        for (int ii = 0; ii < 16; ii++) {
            float4 xv = ((const float4*)xs[ii])[k4];
            acc[ii] = fmaf(b4.x, xv.x, acc[ii]);
            acc[ii] = fmaf(b4.y, xv.y, acc[ii]);
            acc[ii] = fmaf(b4.z, xv.z, acc[ii]);
            acc[ii] = fmaf(b4.w, xv.w, acc[ii]);
        }
    }
#pragma unroll
    for (int ii = 0; ii < 16; ii++)
        out[(size_t)(ib * 16 + ii) * 256 + tid] = scale * acc[ii];
}

__global__ void u_kernel(const float* __restrict__ mem, const float* __restrict__ U) {
    gemm256_body(mem, U, g_u2, TWO_LOG2E);   // pre-scale for tanh exponent
}
__global__ void w_kernel(const float* __restrict__ outp, const float* __restrict__ W) {
    gemm256_body(outp, W, g_w2, TWO_LOG2E);
}

// ---------------- persistent GRU kernel ------------------------------------
// 128 CTAs x 128 threads. CTA b owns e in {2b, 2b+1} -> Whh rows
// {g*256 + 2b + el : g in 0..2, el in 0..1} cached in smem. One grid barrier/step.
__global__ void __launch_bounds__(128, 1)
gru_kernel(const float* __restrict__ h0, const float* __restrict__ Whh,
           const float* __restrict__ bhh,
           float* __restrict__ outp, float* __restrict__ hid) {
    __shared__ float whs[6 * 256];
    __shared__ float hs[8 * 260];       // padded stride 260 -> conflict-light
    __shared__ float ghs[48];

    int tid = threadIdx.x, bid = blockIdx.x;
    int e0 = 2 * bid;

    // load Whh slice (6 rows)
    for (int q = 0; q < 3; q++) {
        int f4 = tid + 128 * q;          // 0..383 (6 rows * 64)
        int lr = f4 >> 6, pos = f4 & 63;
        int g = lr >> 1, el = lr & 1;
        int R = g * 256 + e0 + el;
        ((float4*)(whs + lr * 256))[pos] = ((const float4*)(Whh + (size_t)R * 256))[pos];
    }
    // load h0
    for (int q = 0; q < 4; q++) {
        int f4 = tid + 128 * q;          // 0..511 (8 rows * 64)
        int n = f4 >> 6, pos = f4 & 63;
        float4 hv = ((const float4*)(h0 + n * 256))[pos];
        *(float4*)(hs + n * 260 + pos * 4) = hv;
    }
    __syncthreads();

    int dot = tid >> 1, half = tid & 1;      // threads 0..95: 48 dots, k-split 2
    int n_d = dot & 7, lr_d = dot >> 3;
    int n_e = tid >> 1, el_e = tid & 1;      // threads 0..15: epilogue owners
    int eg = e0 + el_e;
    const float4* wrow = (const float4*)(whs + lr_d * 256) + half * 32;

    // n-gate recurrent bias stays inside the r* product
    float bn = (tid < 16) ? __ldg(bhh + 512 + eg) : 0.f;

    for (int t = 0; t < 300; t++) {
        // prefetch input gates for epilogue (not on h-critical path)
        float ir = 0.f, iz = 0.f, inn = 0.f;
        if (tid < 16) {
            const float* gib = g_gi + (size_t)(t * 8 + n_e) * 768 + eg;
            ir = __ldg(gib); iz = __ldg(gib + 256); inn = __ldg(gib + 512);
        }

        if (tid < 96) {
            const float4* hrow = (const float4*)(hs + n_d * 260) + half * 32;
            float a0 = 0.f, a1 = 0.f, a2 = 0.f, a3 = 0.f;
#pragma unroll
            for (int k4 = 0; k4 < 32; k4++) {
                float4 w4 = wrow[k4];
                float4 h4 = hrow[k4];
                a0 = fmaf(w4.x, h4.x, a0);
                a1 = fmaf(w4.y, h4.y, a1);
                a2 = fmaf(w4.z, h4.z, a2);
                a3 = fmaf(w4.w, h4.w, a3);
            }
            float acc = (a0 + a1) + (a2 + a3);
            acc += __shfl_xor_sync(0xffffffffu, acc, 1);
            if (half == 0) ghs[dot] = acc;
        }
        __syncthreads();

        if (tid < 16) {
            float gr = ghs[(el_e) * 8 + n_e];          // gate 0 (r):  lr = el
            float gz = ghs[(2 + el_e) * 8 + n_e];      // gate 1 (z):  lr = 2+el
            float gn = ghs[(4 + el_e) * 8 + n_e];      // gate 2 (n):  lr = 4+el
            float r  = sigmoidf_(ir + gr);
            float z  = sigmoidf_(iz + gz);
            float nn = tanhf_(fmaf(r, gn + bn, inn));  // n = tanh(i_n + r*(hdot+bhh_n))
            float hold = hs[n_e * 260 + eg];
            float hnew = fmaf(z, hold - nn, nn);
            __stcg(g_hb + ((t + 1) & 1) * 2048 + n_e * 256 + eg, hnew);
            outp[(size_t)(n_e * 300 + t) * 256 + eg] = hnew;
            if (t == 299) hid[n_e * 256 + eg] = hnew;
        }
        if (t == 299) break;
        __syncthreads();

        // grid barrier: release arrive + acquire spin (per-step counter)
        if (tid == 0) {
            asm volatile("red.release.gpu.global.add.u32 [%0], %1;"
                         :: "l"(&g_bar[t]), "r"(1u) : "memory");
        }
        unsigned vv;
        do {
            asm volatile("ld.acquire.gpu.global.u32 %0, [%1];"
                         : "=r"(vv) : "l"(&g_bar[t]) : "memory");
        } while (vv < GRU_CTAS);

        // reload full h (ping-pong buffer; L1-bypassing loads)
        const float* hsrc = g_hb + ((t + 1) & 1) * 2048;
        for (int q = 0; q < 4; q++) {
            int f4 = tid + 128 * q;
            int n = f4 >> 6, pos = f4 & 63;
            float4 hv = __ldcg((const float4*)(hsrc + n * 256) + pos);
            *(float4*)(hs + n * 260 + pos * 4) = hv;
        }
        __syncthreads();
    }
}

// ---------------- barrier cleanup (keeps graph replays deterministic) ------
__global__ void cleanup_kernel() {
    unsigned i = threadIdx.x;
    if (i < 304) g_bar[i] = 0u;
}

// ---------------- attention: scores + softmax -------------------------------
// grid (30, 8) = (t-blocks of 10, n); block 160 (one thread per x)
__global__ void attn_kernel(const float* __restrict__ v, float* __restrict__ attn) {
    __shared__ float w2s[10 * 256];
    __shared__ float vs[256];
    __shared__ float red[8];

    int x = threadIdx.x;                 // 0..159
    int tb = blockIdx.x, n = blockIdx.y;
    int t0 = tb * 10;

    for (int i = x; i < 2560; i += 160)
        w2s[i] = g_w2[(size_t)(n * 300 + t0) * 256 + i];
    for (int i = x; i < 256; i += 160)
        vs[i] = v[i];
    __syncthreads();

    float S;
    {
        float s0 = 0.f, s1 = 0.f, s2 = 0.f, s3 = 0.f;
        for (int e = 0; e < 256; e += 4) {
            s0 += vs[e]; s1 += vs[e + 1]; s2 += vs[e + 2]; s3 += vs[e + 3];
        }
        S = (s0 + s1) + (s2 + s3);
    }

    float acc[10];
#pragma unroll
    for (int tt = 0; tt < 10; tt++) acc[tt] = 0.f;

    const float4* urow = (const float4*)(g_u2 + (size_t)(n * 160 + x) * 256);
    for (int e4 = 0; e4 < 64; e4++) {
        float4 u4 = __ldg(urow + e4);
#pragma unroll
        for (int j = 0; j < 4; j++) {
            float ue = (j == 0) ? u4.x : (j == 1) ? u4.y : (j == 2) ? u4.z : u4.w;
            int e = e4 * 4 + j;
            float ve = vs[e];
#pragma unroll
            for (int tt = 0; tt < 10; tt++) {
                float a = w2s[tt * 256 + e] + ue;      // already * 2*log2e
                float r = rcpf_(1.f + ex2f_(a));       // tanh = 1 - 2r
                acc[tt] = fmaf(ve, r, acc[tt]);
            }
        }
    }

    int lane = x & 31, wid = x >> 5;
    for (int tt = 0; tt < 10; tt++) {
        float sc = fmaf(-2.f, acc[tt], S);
        float m = sc;
#pragma unroll
        for (int o = 16; o > 0; o >>= 1)
            m = fmaxf(m, __shfl_xor_sync(0xffffffffu, m, o));
        if (lane == 0) red[wid] = m;
        __syncthreads();
        m = fmaxf(fmaxf(fmaxf(red[0], red[1]), fmaxf(red[2], red[3])), red[4]);

        float p = ex2f_((sc - m) * LOG2E);
        float s = p;
#pragma unroll
        for (int o = 16; o > 0; o >>= 1)
            s += __shfl_xor_sync(0xffffffffu, s, o);
        __syncthreads();
        if (lane == 0) red[wid] = s;
        __syncthreads();
        s = ((red[0] + red[1]) + (red[2] + red[3])) + red[4];

        attn[(size_t)(n * 300 + t0 + tt) * 160 + x] = p * rcpf_(s);
        __syncthreads();
    }
}

// ---------------- launcher ---------------------------------------------------
extern "C" void kernel_launch(void* const* d_in, const int* in_sizes, int n_in,
                              void* d_out, int out_size) {
    (void)in_sizes; (void)n_in; (void)out_size;
    const float* inputs = (const float*)d_in[0];
    const float* memory = (const float*)d_in[1];
    const float* h0     = (const float*)d_in[2];
    const float* Wih    = (const float*)d_in[3];
    const float* Whh    = (const float*)d_in[4];
    const float* bih    = (const float*)d_in[5];
    const float* bhh    = (const float*)d_in[6];
    const float* W      = (const float*)d_in[7];
    const float* U      = (const float*)d_in[8];
    const float* v      = (const float*)d_in[9];

    float* out     = (float*)d_out;
    float* attn    = out;                 // [8,300,160] = 384000
    float* outputs = out + 384000;        // [8,300,256] = 614400
    float* hidden  = out + 998400;        // [1,8,256]   = 2048

    gi_kernel<<<dim3(150, 3), 256>>>(inputs, Wih, bih, bhh);
    u_kernel<<<80, 256>>>(memory, U);
    gru_kernel<<<GRU_CTAS, 128>>>(h0, Whh, bhh, outputs, hidden);
    cleanup_kernel<<<1, 320>>>();
    w_kernel<<<150, 256>>>(outputs, W);
    attn_kernel<<<dim3(30, 8), 160>>>(v, attn);
}

// round 3
// speedup vs baseline: 1.1835x; 1.1835x over previous
#include <cuda_runtime.h>
#include <cstdint>

#define LOG2E     1.4426950408889634f
#define TWO_LOG2E 2.8853900817779268f
#define GRU_CTAS  128

// ---------------- scratch (device globals: no allocation allowed) ----------
__device__ float    g_gi[2400 * 768];   // pre-GRU input gates  [t*8+n][768]
__device__ float    g_u2[1280 * 256];   // 2*log2e * (memory @ U^T)  [n*160+x][256]
__device__ float    g_w2[2400 * 256];   // 2*log2e * (outputs @ W^T) [n*300+t][256]
__device__ float    g_hb[2 * 8 * 256];  // ping-pong hidden state
__device__ unsigned g_bar[304];         // per-step grid barrier counters

// ---------------- fast math ------------------------------------------------
__device__ __forceinline__ float ex2f_(float x) {
    float y; asm("ex2.approx.f32 %0, %1;" : "=f"(y) : "f"(x)); return y;
}
__device__ __forceinline__ float rcpf_(float x) {
    float y; asm("rcp.approx.f32 %0, %1;" : "=f"(y) : "f"(x)); return y;
}
__device__ __forceinline__ float sigmoidf_(float x) {
    return rcpf_(1.f + ex2f_(-x * LOG2E));
}
__device__ __forceinline__ float tanhf_(float x) {
    // tanh(x) = 1 - 2/(exp(2x)+1); exact at +-inf, ~1e-6 error
    return fmaf(-2.f, rcpf_(1.f + ex2f_(x * TWO_LOG2E)), 1.f);
}

// ---------------- kernel A: gi = inputs @ Wih^T + bih (+bhh for r,z) -------
// out rows indexed i = t*8 + n ; grid (150, 3), block 256
// bhh folded ONLY for gates r,z (jb<2); n-gate recurrent bias stays inside
// the reset product: n = tanh(i_n + r*(hdot + bhh_n)).
__global__ void gi_kernel(const float* __restrict__ inp,
                          const float* __restrict__ Wih,
                          const float* __restrict__ bih,
                          const float* __restrict__ bhh) {
    __shared__ float xs[16][128];
    int tid = threadIdx.x;
    int ib = blockIdx.x, jb = blockIdx.y;
    int j = jb * 256 + tid;

    for (int q = 0; q < 2; q++) {
        int f4 = tid + 256 * q;          // 0..511 float4 slots (16 rows * 32)
        int ii = f4 >> 5, pos = f4 & 31;
        int i = ib * 16 + ii;
        int t = i >> 3, n = i & 7;
        ((float4*)xs[ii])[pos] = ((const float4*)(inp + (n * 300 + t) * 128))[pos];
    }
    __syncthreads();

    float acc[16];
#pragma unroll
    for (int ii = 0; ii < 16; ii++) acc[ii] = 0.f;

    const float4* wr = (const float4*)(Wih + (size_t)j * 128);
    for (int k4 = 0; k4 < 32; k4++) {
        float4 w4 = __ldg(wr + k4);
#pragma unroll
        for (int ii = 0; ii < 16; ii++) {
            float4 xv = ((const float4*)xs[ii])[k4];
            acc[ii] = fmaf(w4.x, xv.x, acc[ii]);
            acc[ii] = fmaf(w4.y, xv.y, acc[ii]);
            acc[ii] = fmaf(w4.z, xv.z, acc[ii]);
            acc[ii] = fmaf(w4.w, xv.w, acc[ii]);
        }
    }
    float b = bih[j] + (jb < 2 ? bhh[j] : 0.f);
#pragma unroll
    for (int ii = 0; ii < 16; ii++)
        g_gi[(size_t)(ib * 16 + ii) * 768 + j] = acc[ii] + b;
}

// ---------------- shared 256-K GEMM body: out[i][j] = scale * A_i . B_j ----
__device__ __forceinline__ void gemm256_body(const float* __restrict__ A,
                                             const float* __restrict__ B,
                                             float* __restrict__ out,
                                             float scale) {
    __shared__ float xs[16][256];
    int tid = threadIdx.x, ib = blockIdx.x;
    for (int q = 0; q < 4; q++) {
        int f4 = tid + 256 * q;          // 0..1023 (16 rows * 64)
        int ii = f4 >> 6, pos = f4 & 63;
        ((float4*)xs[ii])[pos] = ((const float4*)(A + (size_t)(ib * 16 + ii) * 256))[pos];
    }
    __syncthreads();

    float acc[16];
#pragma unroll
    for (int ii = 0; ii < 16; ii++) acc[ii] = 0.f;

    const float4* br = (const float4*)(B + (size_t)tid * 256);
    for (int k4 = 0; k4 < 64; k4++) {
        float4 b4 = __ldg(br + k4);
#pragma unroll
        for (int ii = 0; ii < 16; ii++) {
            float4 xv = ((const float4*)xs[ii])[k4];
            acc[ii] = fmaf(b4.x, xv.x, acc[ii]);
            acc[ii] = fmaf(b4.y, xv.y, acc[ii]);
            acc[ii] = fmaf(b4.z, xv.z, acc[ii]);
            acc[ii] = fmaf(b4.w, xv.w, acc[ii]);
        }
    }
#pragma unroll
    for (int ii = 0; ii < 16; ii++)
        out[(size_t)(ib * 16 + ii) * 256 + tid] = scale * acc[ii];
}

__global__ void u_kernel(const float* __restrict__ mem, const float* __restrict__ U) {
    gemm256_body(mem, U, g_u2, TWO_LOG2E);   // pre-scale for tanh exponent
}
__global__ void w_kernel(const float* __restrict__ outp, const float* __restrict__ W) {
    gemm256_body(outp, W, g_w2, TWO_LOG2E);
}

// ---------------- persistent GRU kernel ------------------------------------
// 128 CTAs x 128 threads. CTA b owns e in {2b, 2b+1}.
// Thread (n = tid>>4, c = tid&15) handles k-chunk [16c,16c+16) of batch n for
// all 6 gate-rows; Whh slice lives in REGISTERS; h is LDG'd straight into
// registers each step (8KB/CTA = the minimum); reduction via shfl.xor.
// One arrival + one spinner (tid 127) per CTA per step.
__global__ void __launch_bounds__(128, 1)
gru_kernel(const float* __restrict__ h0, const float* __restrict__ Whh,
           const float* __restrict__ bhh,
           float* __restrict__ outp, float* __restrict__ hid) {
    __shared__ float hrow_s[8][16];     // h_old[n][16c_h..] staging for epilogue

    int tid = threadIdx.x, bid = blockIdx.x;
    int e0 = 2 * bid;
    int n = tid >> 4, c = tid & 15;

    // Whh slice -> registers: rows lr = 2g+el  (R = g*256 + e0 + el), my k-chunk
    float4 w[6][4];
#pragma unroll
    for (int lr = 0; lr < 6; lr++) {
        int g = lr >> 1, el = lr & 1;
        const float4* wr = (const float4*)(Whh + (size_t)(g * 256 + e0 + el) * 256 + c * 16);
#pragma unroll
        for (int q = 0; q < 4; q++) w[lr][q] = __ldg(wr + q);
    }

    const int c_h = e0 >> 4;            // k-chunk containing e0, e0+1
    const int p0 = e0 & 15;

    const bool is_epi = (c < 2);        // lanes c=0,1 own hidden units e0+c
    const int eg = e0 + c;
    float bn = is_epi ? __ldg(bhh + 512 + eg) : 0.f;

    float ir = 0.f, iz = 0.f, inn = 0.f;
    if (is_epi) {
        const float* gib = g_gi + (size_t)(0 * 8 + n) * 768 + eg;
        ir = __ldg(gib); iz = __ldg(gib + 256); inn = __ldg(gib + 512);
    }

    const float* hsrc = h0 + n * 256 + c * 16;   // t=0 source

    for (int t = 0; t < 300; t++) {
        float4 h4[4];
#pragma unroll
        for (int q = 0; q < 4; q++) h4[q] = __ldcg((const float4*)hsrc + q);

        if (c == c_h) {
#pragma unroll
            for (int q = 0; q < 4; q++)
                *(float4*)&hrow_s[n][q * 4] = h4[q];
        }
        __syncthreads();                 // hrow_s ready for epilogue lanes

        float acc[6];
#pragma unroll
        for (int lr = 0; lr < 6; lr++) acc[lr] = 0.f;
#pragma unroll
        for (int lr = 0; lr < 6; lr++) {
#pragma unroll
            for (int q = 0; q < 4; q++) {
                acc[lr] = fmaf(w[lr][q].x, h4[q].x, acc[lr]);
                acc[lr] = fmaf(w[lr][q].y, h4[q].y, acc[lr]);
                acc[lr] = fmaf(w[lr][q].z, h4[q].z, acc[lr]);
                acc[lr] = fmaf(w[lr][q].w, h4[q].w, acc[lr]);
            }
        }
        // reduce across the 16-lane k-split (xor stays inside each half-warp)
#pragma unroll
        for (int o = 8; o >= 1; o >>= 1) {
#pragma unroll
            for (int lr = 0; lr < 6; lr++)
                acc[lr] += __shfl_xor_sync(0xffffffffu, acc[lr], o);
        }

        if (is_epi) {
            float gr = c ? acc[1] : acc[0];
            float gz = c ? acc[3] : acc[2];
            float gn = c ? acc[5] : acc[4];
            float r  = sigmoidf_(ir + gr);
            float z  = sigmoidf_(iz + gz);
            float nn = tanhf_(fmaf(r, gn + bn, inn));   // n = tanh(i_n + r*(hdot+bhh_n))
            float hold = hrow_s[n][p0 + c];
            float hnew = fmaf(z, hold - nn, nn);
            __stcg(g_hb + ((t + 1) & 1) * 2048 + n * 256 + eg, hnew);
            outp[(size_t)(n * 300 + t) * 256 + eg] = hnew;
            if (t == 299) hid[n * 256 + eg] = hnew;
        }
        if (t == 299) break;

        // prefetch next step's input gates (hides under the barrier)
        if (is_epi) {
            const float* gib = g_gi + (size_t)((t + 1) * 8 + n) * 768 + eg;
            ir = __ldg(gib); iz = __ldg(gib + 256); inn = __ldg(gib + 512);
        }

        __syncthreads();                 // epilogue h stores done CTA-wide
        if (tid == 127) {                // single arrival + single spinner
            asm volatile("red.release.gpu.global.add.u32 [%0], %1;"
                         :: "l"(&g_bar[t]), "r"(1u) : "memory");
            unsigned vv;
            do {
                asm volatile("ld.acquire.gpu.global.u32 %0, [%1];"
                             : "=r"(vv) : "l"(&g_bar[t]) : "memory");
            } while (vv < GRU_CTAS);
        }
        __syncthreads();                 // release everyone past the barrier

        hsrc = g_hb + ((t + 1) & 1) * 2048 + n * 256 + c * 16;
    }
}

// ---------------- barrier cleanup (before gru: resets for every replay) ----
__global__ void cleanup_kernel() {
    unsigned i = threadIdx.x;
    if (i < 304) g_bar[i] = 0u;
}

// ---------------- attention: scores + softmax -------------------------------
// grid (30, 8) = (t-blocks of 10, n); block 160 (one thread per x)
__global__ void attn_kernel(const float* __restrict__ v, float* __restrict__ attn) {
    __shared__ float w2s[10 * 256];
    __shared__ float vs[256];
    __shared__ float red[8];

    int x = threadIdx.x;                 // 0..159
    int tb = blockIdx.x, n = blockIdx.y;
    int t0 = tb * 10;

    for (int i = x; i < 2560; i += 160)
        w2s[i] = g_w2[(size_t)(n * 300 + t0) * 256 + i];
    for (int i = x; i < 256; i += 160)
        vs[i] = v[i];
    __syncthreads();

    float S;
    {
        float s0 = 0.f, s1 = 0.f, s2 = 0.f, s3 = 0.f;
        for (int e = 0; e < 256; e += 4) {
            s0 += vs[e]; s1 += vs[e + 1]; s2 += vs[e + 2]; s3 += vs[e + 3];
        }
        S = (s0 + s1) + (s2 + s3);
    }

    float acc[10];
#pragma unroll
    for (int tt = 0; tt < 10; tt++) acc[tt] = 0.f;

    const float4* urow = (const float4*)(g_u2 + (size_t)(n * 160 + x) * 256);
    for (int e4 = 0; e4 < 64; e4++) {
        float4 u4 = __ldg(urow + e4);
#pragma unroll
        for (int j = 0; j < 4; j++) {
            float ue = (j == 0) ? u4.x : (j == 1) ? u4.y : (j == 2) ? u4.z : u4.w;
            int e = e4 * 4 + j;
            float ve = vs[e];
#pragma unroll
            for (int tt = 0; tt < 10; tt++) {
                float a = w2s[tt * 256 + e] + ue;      // already * 2*log2e
                float r = rcpf_(1.f + ex2f_(a));       // tanh = 1 - 2r
                acc[tt] = fmaf(ve, r, acc[tt]);
            }
        }
    }

    int lane = x & 31, wid = x >> 5;
    for (int tt = 0; tt < 10; tt++) {
        float sc = fmaf(-2.f, acc[tt], S);
        float m = sc;
#pragma unroll
        for (int o = 16; o > 0; o >>= 1)
            m = fmaxf(m, __shfl_xor_sync(0xffffffffu, m, o));
        if (lane == 0) red[wid] = m;
        __syncthreads();
        m = fmaxf(fmaxf(fmaxf(red[0], red[1]), fmaxf(red[2], red[3])), red[4]);

        float p = ex2f_((sc - m) * LOG2E);
        float s = p;
#pragma unroll
        for (int o = 16; o > 0; o >>= 1)
            s += __shfl_xor_sync(0xffffffffu, s, o);
        __syncthreads();
        if (lane == 0) red[wid] = s;
        __syncthreads();
        s = ((red[0] + red[1]) + (red[2] + red[3])) + red[4];

        attn[(size_t)(n * 300 + t0 + tt) * 160 + x] = p * rcpf_(s);
        __syncthreads();
    }
}

// ---------------- launcher ---------------------------------------------------
extern "C" void kernel_launch(void* const* d_in, const int* in_sizes, int n_in,
                              void* d_out, int out_size) {
    (void)in_sizes; (void)n_in; (void)out_size;
    const float* inputs = (const float*)d_in[0];
    const float* memory = (const float*)d_in[1];
    const float* h0     = (const float*)d_in[2];
    const float* Wih    = (const float*)d_in[3];
    const float* Whh    = (const float*)d_in[4];
    const float* bih    = (const float*)d_in[5];
    const float* bhh    = (const float*)d_in[6];
    const float* W      = (const float*)d_in[7];
    const float* U      = (const float*)d_in[8];
    const float* v      = (const float*)d_in[9];

    float* out     = (float*)d_out;
    float* attn    = out;                 // [8,300,160] = 384000
    float* outputs = out + 384000;        // [8,300,256] = 614400
    float* hidden  = out + 998400;        // [1,8,256]   = 2048

    gi_kernel<<<dim3(150, 3), 256>>>(inputs, Wih, bih, bhh);
    u_kernel<<<80, 256>>>(memory, U);
    cleanup_kernel<<<1, 320>>>();
    gru_kernel<<<GRU_CTAS, 128>>>(h0, Whh, bhh, outputs, hidden);
    w_kernel<<<150, 256>>>(outputs, W);
    attn_kernel<<<dim3(30, 8), 160>>>(v, attn);
}